// round 1
// baseline (speedup 1.0000x reference)
#include <cuda_runtime.h>
#include <cuda_bf16.h>
#include <mma.h>

using namespace nvcuda;

// Problem constants
#define NN 8192
#define DD 512
#define NC 100

// ---------------- scratch (device globals; no allocation allowed) ----------
__device__ __nv_bfloat16 g_z16[2][NN * DD];          // bf16 copies of z_a, z_b
__device__ float  g_colsum[2][DD];
__device__ float  g_colsumsq[2][DD];
__device__ float  g_clssum[2][NC * DD];              // raw per-class column sums
__device__ float  g_gram[2][DD * DD];                // raw Grams Z^T Z
__device__ float  g_mu[2][DD];
__device__ float  g_is[2][DD];                       // 1/std (ddof=1)
__device__ int    g_cnt[NC];
__device__ int    g_is64;
__device__ double g_acc[2];                          // [0]=t1, [1]=cross

__device__ __forceinline__ int get_label(const int* L, int i) {
    return g_is64 ? L[2 * i] : L[i];
}

// ---------------- K0: zero accumulators, detect label dtype ----------------
__global__ void k_init(const int* labels_raw) {
    int tid = blockIdx.x * blockDim.x + threadIdx.x;
    int stride = gridDim.x * blockDim.x;
    float* gr = &g_gram[0][0];
    for (int i = tid; i < 2 * DD * DD; i += stride) gr[i] = 0.0f;
    float* cs = &g_clssum[0][0];
    for (int i = tid; i < 2 * NC * DD; i += stride) cs[i] = 0.0f;
    float* c1 = &g_colsum[0][0];
    float* c2 = &g_colsumsq[0][0];
    for (int i = tid; i < 2 * DD; i += stride) { c1[i] = 0.0f; c2[i] = 0.0f; }
    if (tid < NC) g_cnt[tid] = 0;
    if (tid < 2)  g_acc[tid] = 0.0;
    if (tid == 0) {
        // int64 labels (values < 100) have all-zero high dwords at odd indices.
        int all0 = 1;
        for (int j = 1; j < 128; j += 2) if (labels_raw[j] != 0) { all0 = 0; break; }
        g_is64 = all0;
    }
}

// ---------------- K1: fp32 -> bf16 convert + column sum/sumsq --------------
// grid (4 col-tiles, 32 row-tiles, 2 tensors), block 256
__global__ void k_convert_stats(const float* __restrict__ za,
                                const float* __restrict__ zb) {
    int which = blockIdx.z;
    const float* z = which ? zb : za;
    __nv_bfloat16* o = g_z16[which];

    int t    = threadIdx.x;
    int col  = t & 127;
    int half = t >> 7;           // 0 or 1
    int c0   = blockIdx.x * 128;
    int r0   = blockIdx.y * 256;

    float s = 0.0f, sq = 0.0f;
    for (int r = half; r < 256; r += 2) {
        int idx = (r0 + r) * DD + c0 + col;
        float v = z[idx];
        o[idx] = __float2bfloat16(v);
        s  += v;
        sq += v * v;
    }
    __shared__ float ssum[256], ssq[256];
    ssum[t] = s; ssq[t] = sq;
    __syncthreads();
    if (half == 0) {
        s  = ssum[t] + ssum[t + 128];
        sq = ssq[t]  + ssq[t + 128];
        atomicAdd(&g_colsum[which][c0 + col], s);
        atomicAdd(&g_colsumsq[which][c0 + col], sq);
    }
}

// ---------------- K2: per-class raw column sums ----------------------------
// grid (8 col-tiles of 64, 4 row-chunks of 2048, 2 tensors), block 256
__global__ void k_classsum(const float* __restrict__ za,
                           const float* __restrict__ zb,
                           const int* __restrict__ labels) {
    int which = blockIdx.z;
    const float* z = which ? zb : za;

    __shared__ float scls[NC * 64];
    int t = threadIdx.x;
    for (int i = t; i < NC * 64; i += 256) scls[i] = 0.0f;
    __syncthreads();

    int col = t & 63;
    int rg  = t >> 6;            // 0..3
    int c0  = blockIdx.x * 64;
    int r0  = blockIdx.y * 2048;

    for (int rr = rg; rr < 2048; rr += 4) {
        int row = r0 + rr;
        int l = get_label(labels, row);
        atomicAdd(&scls[l * 64 + col], z[row * DD + c0 + col]);
    }
    __syncthreads();
    for (int i = t; i < NC * 64; i += 256) {
        float v = scls[i];
        if (v != 0.0f) {
            int k = i >> 6, cc = i & 63;
            atomicAdd(&g_clssum[which][k * DD + c0 + cc], v);
        }
    }
}

// ---------------- K3: bf16 Gram (Z^T Z) via wmma ---------------------------
// grid (16 tiles (4x4), 8 k-splits, 2 tensors), block 256 (8 warps 4x2)
__global__ void k_gram(void) {
    const int which = blockIdx.z;
    const __nv_bfloat16* __restrict__ src = g_z16[which];
    float* __restrict__ gout = g_gram[which];

    const int tile = blockIdx.x;
    const int m0 = (tile & 3) * 128;
    const int n0 = (tile >> 2) * 128;
    const int kbase = blockIdx.y * 1024;

    const int t = threadIdx.x;
    const int warpId = t >> 5;
    const int lane = t & 31;
    const int wm = warpId & 3;      // 4 warps in m
    const int wn = warpId >> 2;     // 2 warps in n

    __shared__ __nv_bfloat16 sA[32 * 128];
    __shared__ __nv_bfloat16 sB[32 * 128];

    wmma::fragment<wmma::accumulator, 16, 16, 16, float> acc[2][4];
#pragma unroll
    for (int i = 0; i < 2; i++)
#pragma unroll
        for (int j = 0; j < 4; j++) wmma::fill_fragment(acc[i][j], 0.0f);

    for (int kc = 0; kc < 1024; kc += 32) {
        __syncthreads();
        // load 32x128 A-tile and B-tile (16B vectors)
#pragma unroll
        for (int v = t; v < 512; v += 256) {
            int k = v >> 4, c8 = v & 15;
            const uint4* ga = (const uint4*)&src[(kbase + kc + k) * DD + m0 + c8 * 8];
            ((uint4*)sA)[v] = *ga;
            const uint4* gb = (const uint4*)&src[(kbase + kc + k) * DD + n0 + c8 * 8];
            ((uint4*)sB)[v] = *gb;
        }
        __syncthreads();

#pragma unroll
        for (int ks = 0; ks < 32; ks += 16) {
            wmma::fragment<wmma::matrix_a, 16, 16, 16, __nv_bfloat16, wmma::col_major> a_frag[2];
            wmma::fragment<wmma::matrix_b, 16, 16, 16, __nv_bfloat16, wmma::row_major> b_frag[4];
#pragma unroll
            for (int i = 0; i < 2; i++)
                wmma::load_matrix_sync(a_frag[i], sA + ks * 128 + wm * 32 + i * 16, 128);
#pragma unroll
            for (int j = 0; j < 4; j++)
                wmma::load_matrix_sync(b_frag[j], sB + ks * 128 + wn * 64 + j * 16, 128);
#pragma unroll
            for (int i = 0; i < 2; i++)
#pragma unroll
                for (int j = 0; j < 4; j++)
                    wmma::mma_sync(acc[i][j], a_frag[i], b_frag[j], acc[i][j]);
        }
    }

    // epilogue: stage each 16x16 fragment in smem, atomicAdd to global
    __shared__ float sC[8][256];
#pragma unroll
    for (int i = 0; i < 2; i++) {
#pragma unroll
        for (int j = 0; j < 4; j++) {
            wmma::store_matrix_sync(&sC[warpId][0], acc[i][j], 16, wmma::mem_row_major);
            __syncwarp();
            int mb = m0 + wm * 32 + i * 16;
            int nb = n0 + wn * 64 + j * 16;
#pragma unroll
            for (int e = lane; e < 256; e += 32) {
                int rr = e >> 4, cc = e & 15;
                atomicAdd(&gout[(mb + rr) * DD + nb + cc], sC[warpId][e]);
            }
            __syncwarp();
        }
    }
}

// ---------------- K4: column stats + label histogram -----------------------
__global__ void k_stats(const int* __restrict__ labels) {
    int t = threadIdx.x;
    if (t < DD) {
#pragma unroll
        for (int w = 0; w < 2; w++) {
            float mu  = g_colsum[w][t] * (1.0f / (float)NN);
            float var = (g_colsumsq[w][t] - (float)NN * mu * mu) * (1.0f / (float)(NN - 1));
            g_mu[w][t] = mu;
            g_is[w][t] = (float)(1.0 / sqrt((double)var));
        }
    }
    for (int i = t; i < NN; i += blockDim.x)
        atomicAdd(&g_cnt[get_label(labels, i)], 1);
}

// ---------------- K5: big reductions (t1, cross) ---------------------------
// grid 128, block 256
__global__ void k_reduce(void) {
    int gid = blockIdx.x * 256 + threadIdx.x;
    const int GSZ = 128 * 256;

    const float* __restrict__ mua = g_mu[0];
    const float* __restrict__ mub = g_mu[1];
    const float* __restrict__ isa = g_is[0];
    const float* __restrict__ isb = g_is[1];

    double t1 = 0.0;
    for (int idx = gid; idx < DD * DD; idx += GSZ) {
        int p = idx >> 9, q = idx & (DD - 1);
        float ga = isa[p] * isa[q] * (g_gram[0][idx] - (float)NN * mua[p] * mua[q]);
        float gb = isb[p] * isb[q] * (g_gram[1][idx] - (float)NN * mub[p] * mub[q]);
        t1 += (double)(ga * gb);
    }

    double cr = 0.0;
    for (int idx = gid; idx < NC * DD; idx += GSZ) {
        int k = idx >> 9, p = idx & (DD - 1);
        float nk = (float)g_cnt[k];
        float u = isa[p] * (g_clssum[0][idx] - nk * mua[p]);
        float v = isb[p] * (g_clssum[1][idx] - nk * mub[p]);
        cr += (double)(u * v);
    }

    __shared__ double st1[256], scr[256];
    int t = threadIdx.x;
    st1[t] = t1; scr[t] = cr;
    __syncthreads();
    for (int s = 128; s > 0; s >>= 1) {
        if (t < s) { st1[t] += st1[t + s]; scr[t] += scr[t + s]; }
        __syncthreads();
    }
    if (t == 0) {
        atomicAdd(&g_acc[0], st1[0]);
        atomicAdd(&g_acc[1], scr[0]);
    }
}

// ---------------- K6: finalize ---------------------------------------------
__global__ void k_final(float* __restrict__ out) {
    double m2 = 0.0;
    for (int k = 0; k < NC; k++) {
        double n = (double)g_cnt[k];
        m2 += n * n;
    }
    double loss = g_acc[0] / ((double)DD * (double)DD)
                - 2.0 * g_acc[1] / (double)DD
                + m2;
    out[0] = (float)loss;
}

// ---------------- launch ----------------------------------------------------
extern "C" void kernel_launch(void* const* d_in, const int* in_sizes, int n_in,
                              void* d_out, int out_size) {
    const float* za = (const float*)d_in[0];
    const float* zb = (const float*)d_in[1];
    const int* labels = (const int*)d_in[2];
    float* out = (float*)d_out;

    k_init<<<512, 256>>>(labels);
    {
        dim3 g(4, 32, 2);
        k_convert_stats<<<g, 256>>>(za, zb);
    }
    {
        dim3 g(8, 4, 2);
        k_classsum<<<g, 256>>>(za, zb, labels);
    }
    {
        dim3 g(16, 8, 2);
        k_gram<<<g, 256>>>();
    }
    k_stats<<<1, 512>>>(labels);
    k_reduce<<<128, 256>>>();
    k_final<<<1, 1>>>(out);
}

// round 2
// speedup vs baseline: 1.3401x; 1.3401x over previous
#include <cuda_runtime.h>
#include <cuda_bf16.h>
#include <mma.h>

using namespace nvcuda;

#define NN 8192
#define DD 512
#define NC 100

// ---------------- scratch ---------------------------------------------------
__device__ __nv_bfloat16 g_z16t[2][DD * NN];   // transposed bf16: [d][n]
__device__ float  g_colsum[2][DD];
__device__ float  g_colsumsq[2][DD];
__device__ float  g_clssum[2][NC * DD];
__device__ float  g_gram[2][DD * DD];
__device__ float  g_mu[2][DD];
__device__ float  g_is[2][DD];
__device__ int    g_cnt[NC];
__device__ int    g_is64;
__device__ double g_acc[2];

__device__ __forceinline__ int get_label(const int* L, int i) {
    return g_is64 ? L[2 * i] : L[i];
}

// ---------------- K0: zero accumulators, detect label dtype ----------------
__global__ void k_init(const int* labels_raw) {
    int tid = blockIdx.x * blockDim.x + threadIdx.x;
    int stride = gridDim.x * blockDim.x;
    float* gr = &g_gram[0][0];
    for (int i = tid; i < 2 * DD * DD; i += stride) gr[i] = 0.0f;
    float* cs = &g_clssum[0][0];
    for (int i = tid; i < 2 * NC * DD; i += stride) cs[i] = 0.0f;
    float* c1 = &g_colsum[0][0];
    float* c2 = &g_colsumsq[0][0];
    for (int i = tid; i < 2 * DD; i += stride) { c1[i] = 0.0f; c2[i] = 0.0f; }
    if (tid < NC) g_cnt[tid] = 0;
    if (tid < 2)  g_acc[tid] = 0.0;
    if (tid == 0) {
        int all0 = 1;
        for (int j = 1; j < 128; j += 2) if (labels_raw[j] != 0) { all0 = 0; break; }
        g_is64 = all0;
    }
}

// ---------------- K1: convert fp32 -> bf16 TRANSPOSED + column stats -------
// grid (64 n-tiles, 4 d-tiles, 2), block 256
__global__ void k_convert_T(const float* __restrict__ za,
                            const float* __restrict__ zb) {
    int which = blockIdx.z;
    const float* z = which ? zb : za;
    __nv_bfloat16* o = g_z16t[which];

    // st[col][r] holds value(n=n0+r, d=d0+col); XOR swizzle on 8-elem groups.
    __shared__ __nv_bfloat16 st[128 * 128];
    __shared__ float ssum[256], ssq[256];

    int t = threadIdx.x;
    int col = t & 127;          // d within tile
    int rh  = t >> 7;           // 0/1
    int n0 = blockIdx.x * 128;
    int d0 = blockIdx.y * 128;

    float s = 0.0f, sq = 0.0f;
    int sw = col & 15;
    for (int r = rh; r < 128; r += 2) {
        float v = z[(n0 + r) * DD + d0 + col];
        int idx = col * 128 + (((r >> 3) ^ sw) << 3) + (r & 7);
        st[idx] = __float2bfloat16(v);
        s += v; sq += v * v;
    }
    ssum[t] = s; ssq[t] = sq;
    __syncthreads();
    if (rh == 0) {
        atomicAdd(&g_colsum[which][d0 + col], ssum[t] + ssum[t + 128]);
        atomicAdd(&g_colsumsq[which][d0 + col], ssq[t] + ssq[t + 128]);
    }
    // write out: 128 d-rows x 16 uint4 (8 bf16 n-values each)
    for (int v = t; v < 128 * 16; v += 256) {
        int dr = v >> 4;        // d within tile
        int og = v & 15;        // logical n-group
        int pg = og ^ (dr & 15);
        uint4 val = *(const uint4*)&st[dr * 128 + pg * 8];
        *(uint4*)&o[(size_t)(d0 + dr) * NN + n0 + og * 8] = val;
    }
}

// ---------------- K2: label histogram --------------------------------------
__global__ void k_hist(const int* __restrict__ labels) {
    __shared__ int h[NC];
    int t = threadIdx.x;
    if (t < NC) h[t] = 0;
    __syncthreads();
    for (int i = blockIdx.x * 512 + t; i < NN; i += gridDim.x * 512)
        atomicAdd(&h[get_label(labels, i)], 1);
    __syncthreads();
    if (t < NC && h[t]) atomicAdd(&g_cnt[t], h[t]);
}

// ---------------- K3: per-class column sums from bf16 transposed -----------
// grid (8 p-tiles of 64, 8 k-chunks of 1024, 2), block 256
__global__ void k_classsum(const int* __restrict__ labels) {
    int which = blockIdx.z;
    __shared__ float scls[NC * 64];
    __shared__ int slab[1024];

    int t = threadIdx.x;
    for (int i = t; i < NC * 64; i += 256) scls[i] = 0.0f;
    int p0 = blockIdx.x * 64;
    int k0 = blockIdx.y * 1024;
    for (int i = t; i < 1024; i += 256) slab[i] = get_label(labels, k0 + i);
    __syncthreads();

    int kk = t & 63, pg = t >> 6;
    for (int p = pg; p < 64; p += 4) {
        const __nv_bfloat16* row = &g_z16t[which][(size_t)(p0 + p) * NN + k0];
        for (int kb = 0; kb < 1024; kb += 64) {
            float v = __bfloat162float(row[kb + kk]);
            atomicAdd(&scls[slab[kb + kk] * 64 + p], v);
        }
    }
    __syncthreads();
    for (int i = t; i < NC * 64; i += 256) {
        float v = scls[i];
        if (v != 0.0f)
            atomicAdd(&g_clssum[which][(i >> 6) * DD + p0 + (i & 63)], v);
    }
}

// ---------------- K4: symmetric bf16 Gram via wmma -------------------------
// upper-triangle 128x128 tiles only; warp tile 64x64; grid (10, 32, 2), blk 128
__constant__ int c_mt[10] = {0,0,0,0,1,1,1,2,2,3};
__constant__ int c_nt[10] = {0,1,2,3,1,2,3,2,3,3};

__global__ void __launch_bounds__(128) k_gram(void) {
    const int which = blockIdx.z;
    const __nv_bfloat16* __restrict__ src = g_z16t[which];
    float* __restrict__ gout = g_gram[which];

    const int m0 = c_mt[blockIdx.x] * 128;
    const int n0 = c_nt[blockIdx.x] * 128;
    const int kbase = blockIdx.y * 256;      // KSPLIT=32 -> 256 K per block

    const int t = threadIdx.x;
    const int warpId = t >> 5;
    const int lane = t & 31;
    const int wm = warpId & 1;     // 2 warps in m
    const int wn = warpId >> 1;    // 2 warps in n

    __shared__ __nv_bfloat16 sA[128 * 72];
    __shared__ __nv_bfloat16 sB[128 * 72];
    __shared__ float sC[4][256];

    wmma::fragment<wmma::accumulator, 16, 16, 16, float> acc[4][4];
#pragma unroll
    for (int i = 0; i < 4; i++)
#pragma unroll
        for (int j = 0; j < 4; j++) wmma::fill_fragment(acc[i][j], 0.0f);

    for (int kc = 0; kc < 256; kc += 64) {
        __syncthreads();
        // stage 128 rows x 64 k (A from m0, B from n0), 16B vectors
#pragma unroll
        for (int v = t; v < 128 * 8; v += 128) {
            int row = v >> 3, kv = v & 7;
            *(uint4*)&sA[row * 72 + kv * 8] =
                *(const uint4*)&src[(size_t)(m0 + row) * NN + kbase + kc + kv * 8];
            *(uint4*)&sB[row * 72 + kv * 8] =
                *(const uint4*)&src[(size_t)(n0 + row) * NN + kbase + kc + kv * 8];
        }
        __syncthreads();

#pragma unroll
        for (int ks = 0; ks < 64; ks += 16) {
            wmma::fragment<wmma::matrix_a, 16, 16, 16, __nv_bfloat16, wmma::row_major> a_frag[4];
            wmma::fragment<wmma::matrix_b, 16, 16, 16, __nv_bfloat16, wmma::col_major> b_frag[4];
#pragma unroll
            for (int i = 0; i < 4; i++)
                wmma::load_matrix_sync(a_frag[i], sA + (wm * 64 + i * 16) * 72 + ks, 72);
#pragma unroll
            for (int j = 0; j < 4; j++)
                wmma::load_matrix_sync(b_frag[j], sB + (wn * 64 + j * 16) * 72 + ks, 72);
#pragma unroll
            for (int i = 0; i < 4; i++)
#pragma unroll
                for (int j = 0; j < 4; j++)
                    wmma::mma_sync(acc[i][j], a_frag[i], b_frag[j], acc[i][j]);
        }
    }

    // epilogue: stage 16x16 fragments, atomicAdd
#pragma unroll
    for (int i = 0; i < 4; i++) {
#pragma unroll
        for (int j = 0; j < 4; j++) {
            wmma::store_matrix_sync(&sC[warpId][0], acc[i][j], 16, wmma::mem_row_major);
            __syncwarp();
            int mb = m0 + wm * 64 + i * 16;
            int nb = n0 + wn * 64 + j * 16;
#pragma unroll
            for (int e = lane; e < 256; e += 32)
                atomicAdd(&gout[(mb + (e >> 4)) * DD + nb + (e & 15)], sC[warpId][e]);
            __syncwarp();
        }
    }
}

// ---------------- K5: column stats -----------------------------------------
__global__ void k_stats(void) {
    int t = threadIdx.x;
    if (t < DD) {
#pragma unroll
        for (int w = 0; w < 2; w++) {
            float mu  = g_colsum[w][t] * (1.0f / (float)NN);
            float var = (g_colsumsq[w][t] - (float)NN * mu * mu) * (1.0f / (float)(NN - 1));
            g_mu[w][t] = mu;
            g_is[w][t] = (float)(1.0 / sqrt((double)var));
        }
    }
}

// ---------------- K6: reductions (symmetric-weighted t1 + cross) -----------
__global__ void k_reduce(void) {
    int gid = blockIdx.x * 256 + threadIdx.x;
    const int GSZ = 128 * 256;

    const float* __restrict__ mua = g_mu[0];
    const float* __restrict__ mub = g_mu[1];
    const float* __restrict__ isa = g_is[0];
    const float* __restrict__ isb = g_is[1];

    double t1 = 0.0;
    for (int idx = gid; idx < DD * DD; idx += GSZ) {
        int p = idx >> 9, q = idx & (DD - 1);
        int tp = p >> 7, tq = q >> 7;
        if (tp > tq) continue;          // only computed tiles
        float w = (tp == tq) ? 1.0f : 2.0f;
        float ga = isa[p] * isa[q] * (g_gram[0][idx] - (float)NN * mua[p] * mua[q]);
        float gb = isb[p] * isb[q] * (g_gram[1][idx] - (float)NN * mub[p] * mub[q]);
        t1 += (double)(w * ga * gb);
    }

    double cr = 0.0;
    for (int idx = gid; idx < NC * DD; idx += GSZ) {
        int k = idx >> 9, p = idx & (DD - 1);
        float nk = (float)g_cnt[k];
        float u = isa[p] * (g_clssum[0][idx] - nk * mua[p]);
        float v = isb[p] * (g_clssum[1][idx] - nk * mub[p]);
        cr += (double)(u * v);
    }

    __shared__ double st1[256], scr[256];
    int t = threadIdx.x;
    st1[t] = t1; scr[t] = cr;
    __syncthreads();
    for (int s = 128; s > 0; s >>= 1) {
        if (t < s) { st1[t] += st1[t + s]; scr[t] += scr[t + s]; }
        __syncthreads();
    }
    if (t == 0) {
        atomicAdd(&g_acc[0], st1[0]);
        atomicAdd(&g_acc[1], scr[0]);
    }
}

// ---------------- K7: finalize ---------------------------------------------
__global__ void k_final(float* __restrict__ out) {
    double m2 = 0.0;
    for (int k = 0; k < NC; k++) {
        double n = (double)g_cnt[k];
        m2 += n * n;
    }
    double loss = g_acc[0] / ((double)DD * (double)DD)
                - 2.0 * g_acc[1] / (double)DD
                + m2;
    out[0] = (float)loss;
}

// ---------------- launch ----------------------------------------------------
extern "C" void kernel_launch(void* const* d_in, const int* in_sizes, int n_in,
                              void* d_out, int out_size) {
    const float* za = (const float*)d_in[0];
    const float* zb = (const float*)d_in[1];
    const int* labels = (const int*)d_in[2];
    float* out = (float*)d_out;

    k_init<<<512, 256>>>(labels);
    { dim3 g(64, 4, 2); k_convert_T<<<g, 256>>>(za, zb); }
    k_hist<<<16, 512>>>(labels);
    { dim3 g(8, 8, 2); k_classsum<<<g, 256>>>(labels); }
    { dim3 g(10, 32, 2); k_gram<<<g, 128>>>(); }
    k_stats<<<1, 512>>>();
    k_reduce<<<128, 256>>>();
    k_final<<<1, 1>>>(out);
}

// round 4
// speedup vs baseline: 2.4990x; 1.8648x over previous
#include <cuda_runtime.h>
#include <cuda_bf16.h>
#include <mma.h>

using namespace nvcuda;

#define NN 8192
#define DD 512
#define NC 100
#define NCP 128   // padded classes

// ---------------- scratch ---------------------------------------------------
__device__ __nv_bfloat16 g_z16t[2][DD * NN];    // transposed bf16: [d][n]
__device__ __nv_bfloat16 g_onehot[NCP * NN];    // one-hot labels, bf16
__device__ float  g_colsum[2][DD];
__device__ float  g_colsumsq[2][DD];
__device__ float  g_clsraw[2][NCP * DD];        // raw class sums (onehot @ z)
__device__ float  g_gram[2][DD * DD];
__device__ float  g_mu[2][DD];
__device__ float  g_is[2][DD];
__device__ int    g_cnt[NC];
__device__ int    g_is64;
__device__ double g_acc[2];

__device__ __forceinline__ int get_label(const int* L, int i) {
    return g_is64 ? L[2 * i] : L[i];
}

// ---------------- K0: zero accumulators + onehot, detect label dtype -------
__global__ void k_init(const int* labels_raw) {
    int tid = blockIdx.x * blockDim.x + threadIdx.x;
    int stride = gridDim.x * blockDim.x;
    float* gr = &g_gram[0][0];
    for (int i = tid; i < 2 * DD * DD; i += stride) gr[i] = 0.0f;
    float* cs = &g_clsraw[0][0];
    for (int i = tid; i < 2 * NCP * DD; i += stride) cs[i] = 0.0f;
    unsigned int* oh = (unsigned int*)&g_onehot[0];
    for (int i = tid; i < NCP * NN / 2; i += stride) oh[i] = 0u;
    float* c1 = &g_colsum[0][0];
    float* c2 = &g_colsumsq[0][0];
    for (int i = tid; i < 2 * DD; i += stride) { c1[i] = 0.0f; c2[i] = 0.0f; }
    if (tid < NC) g_cnt[tid] = 0;
    if (tid < 2)  g_acc[tid] = 0.0;
    if (tid == 0) {
        int all0 = 1;
        for (int j = 1; j < 128; j += 2) if (labels_raw[j] != 0) { all0 = 0; break; }
        g_is64 = all0;
    }
}

// ---------------- K0b: scatter one-hot + histogram -------------------------
__global__ void k_scatter(const int* __restrict__ labels) {
    __shared__ int h[NC];
    int t = threadIdx.x;
    if (t < NC) h[t] = 0;
    __syncthreads();
    int n = blockIdx.x * 512 + t;
    if (n < NN) {
        int l = get_label(labels, n);
        g_onehot[(size_t)l * NN + n] = __float2bfloat16(1.0f);
        atomicAdd(&h[l], 1);
    }
    __syncthreads();
    if (t < NC && h[t]) atomicAdd(&g_cnt[t], h[t]);
}

// ---------------- K1: convert fp32 -> bf16 TRANSPOSED + column stats -------
// grid (64 n-tiles, 4 d-tiles, 2), block 256
__global__ void k_convert_T(const float* __restrict__ za,
                            const float* __restrict__ zb) {
    int which = blockIdx.z;
    const float* z = which ? zb : za;
    __nv_bfloat16* o = g_z16t[which];

    __shared__ __nv_bfloat16 st[128 * 128];
    __shared__ float ssum[256], ssq[256];

    int t = threadIdx.x;
    int col = t & 127;          // d within tile
    int rh  = t >> 7;
    int n0 = blockIdx.x * 128;
    int d0 = blockIdx.y * 128;

    float s = 0.0f, sq = 0.0f;
    int sw = col & 15;
    for (int r = rh; r < 128; r += 2) {
        float v = z[(n0 + r) * DD + d0 + col];
        int idx = col * 128 + (((r >> 3) ^ sw) << 3) + (r & 7);
        st[idx] = __float2bfloat16(v);
        s += v; sq += v * v;
    }
    ssum[t] = s; ssq[t] = sq;
    __syncthreads();
    if (rh == 0) {
        atomicAdd(&g_colsum[which][d0 + col], ssum[t] + ssum[t + 128]);
        atomicAdd(&g_colsumsq[which][d0 + col], ssq[t] + ssq[t + 128]);
    }
    for (int v = t; v < 128 * 16; v += 256) {
        int dr = v >> 4;
        int og = v & 15;
        int pg = og ^ (dr & 15);
        uint4 val = *(const uint4*)&st[dr * 128 + pg * 8];
        *(uint4*)&o[(size_t)(d0 + dr) * NN + n0 + og * 8] = val;
    }
}

// ---------------- shared wmma GEMM body ------------------------------------
// Computes C[128 x 128] += A128rows . B128rows^T over K-chunk, both K-major.
// block 128 threads (4 warps, 2x2), warp tile 64x64.
template <int KLEN>
__device__ __forceinline__ void gemm128x128(
    const __nv_bfloat16* __restrict__ arow,  // &A[row0 * NN + kbase]
    const __nv_bfloat16* __restrict__ brow,  // &B[col0 * NN + kbase]
    float* __restrict__ cout,                // &C[0], ld DD
    int mb0, int nb0)
{
    const int t = threadIdx.x;
    const int warpId = t >> 5;
    const int lane = t & 31;
    const int wm = warpId & 1;
    const int wn = warpId >> 1;

    __shared__ __nv_bfloat16 sA[128 * 72];
    __shared__ __nv_bfloat16 sB[128 * 72];
    __shared__ float sC[4][256];

    wmma::fragment<wmma::accumulator, 16, 16, 16, float> acc[4][4];
#pragma unroll
    for (int i = 0; i < 4; i++)
#pragma unroll
        for (int j = 0; j < 4; j++) wmma::fill_fragment(acc[i][j], 0.0f);

    for (int kc = 0; kc < KLEN; kc += 64) {
        __syncthreads();
#pragma unroll
        for (int v = t; v < 128 * 8; v += 128) {
            int row = v >> 3, kv = v & 7;
            *(uint4*)&sA[row * 72 + kv * 8] =
                *(const uint4*)&arow[(size_t)row * NN + kc + kv * 8];
            *(uint4*)&sB[row * 72 + kv * 8] =
                *(const uint4*)&brow[(size_t)row * NN + kc + kv * 8];
        }
        __syncthreads();

#pragma unroll
        for (int ks = 0; ks < 64; ks += 16) {
            wmma::fragment<wmma::matrix_a, 16, 16, 16, __nv_bfloat16, wmma::row_major> a_frag[4];
            wmma::fragment<wmma::matrix_b, 16, 16, 16, __nv_bfloat16, wmma::col_major> b_frag[4];
#pragma unroll
            for (int i = 0; i < 4; i++)
                wmma::load_matrix_sync(a_frag[i], sA + (wm * 64 + i * 16) * 72 + ks, 72);
#pragma unroll
            for (int j = 0; j < 4; j++)
                wmma::load_matrix_sync(b_frag[j], sB + (wn * 64 + j * 16) * 72 + ks, 72);
#pragma unroll
            for (int i = 0; i < 4; i++)
#pragma unroll
                for (int j = 0; j < 4; j++)
                    wmma::mma_sync(acc[i][j], a_frag[i], b_frag[j], acc[i][j]);
        }
    }

#pragma unroll
    for (int i = 0; i < 4; i++) {
#pragma unroll
        for (int j = 0; j < 4; j++) {
            wmma::store_matrix_sync(&sC[warpId][0], acc[i][j], 16, wmma::mem_row_major);
            __syncwarp();
            int mb = mb0 + wm * 64 + i * 16;
            int nb = nb0 + wn * 64 + j * 16;
#pragma unroll
            for (int e = lane; e < 256; e += 32)
                atomicAdd(&cout[(mb + (e >> 4)) * DD + nb + (e & 15)], sC[warpId][e]);
            __syncwarp();
        }
    }
}

// ---------------- K4: symmetric bf16 Gram ----------------------------------
// upper-triangle tiles; grid (10, 32, 2), block 128
__constant__ int c_mt[10] = {0,0,0,0,1,1,1,2,2,3};
__constant__ int c_nt[10] = {0,1,2,3,1,2,3,2,3,3};

__global__ void __launch_bounds__(128) k_gram(void) {
    const int which = blockIdx.z;
    const __nv_bfloat16* src = g_z16t[which];
    const int m0 = c_mt[blockIdx.x] * 128;
    const int n0 = c_nt[blockIdx.x] * 128;
    const int kbase = blockIdx.y * 256;
    gemm128x128<256>(src + (size_t)m0 * NN + kbase,
                     src + (size_t)n0 * NN + kbase,
                     g_gram[which], m0, n0);
}

// ---------------- K3: class sums = onehot @ z^T (GEMM) ---------------------
// grid (4 p-tiles, 16 k-splits, 2), block 128
__global__ void __launch_bounds__(128) k_clsgemm(void) {
    const int which = blockIdx.z;
    const int n0 = blockIdx.x * 128;       // p-tile
    const int kbase = blockIdx.y * 512;
    gemm128x128<512>(g_onehot + kbase,
                     g_z16t[which] + (size_t)n0 * NN + kbase,
                     g_clsraw[which], 0, n0);
}

// ---------------- K5: column stats -----------------------------------------
__global__ void k_stats(void) {
    int t = threadIdx.x;
    if (t < DD) {
#pragma unroll
        for (int w = 0; w < 2; w++) {
            float mu  = g_colsum[w][t] * (1.0f / (float)NN);
            float var = (g_colsumsq[w][t] - (float)NN * mu * mu) * (1.0f / (float)(NN - 1));
            g_mu[w][t] = mu;
            g_is[w][t] = (float)(1.0 / sqrt((double)var));
        }
    }
}

// ---------------- K6: reductions -------------------------------------------
__global__ void k_reduce(void) {
    int gid = blockIdx.x * 256 + threadIdx.x;
    const int GSZ = 128 * 256;

    const float* __restrict__ mua = g_mu[0];
    const float* __restrict__ mub = g_mu[1];
    const float* __restrict__ isa = g_is[0];
    const float* __restrict__ isb = g_is[1];

    double t1 = 0.0;
    for (int idx = gid; idx < DD * DD; idx += GSZ) {
        int p = idx >> 9, q = idx & (DD - 1);
        int tp = p >> 7, tq = q >> 7;
        if (tp > tq) continue;
        float w = (tp == tq) ? 1.0f : 2.0f;
        float ga = isa[p] * isa[q] * (g_gram[0][idx] - (float)NN * mua[p] * mua[q]);
        float gb = isb[p] * isb[q] * (g_gram[1][idx] - (float)NN * mub[p] * mub[q]);
        t1 += (double)(w * ga * gb);
    }

    double cr = 0.0;
    for (int idx = gid; idx < NC * DD; idx += GSZ) {
        int k = idx >> 9, p = idx & (DD - 1);
        float nk = (float)g_cnt[k];
        float u = isa[p] * (g_clsraw[0][k * DD + p] - nk * mua[p]);
        float v = isb[p] * (g_clsraw[1][k * DD + p] - nk * mub[p]);
        cr += (double)(u * v);
    }

    __shared__ double st1[256], scr[256];
    int t = threadIdx.x;
    st1[t] = t1; scr[t] = cr;
    __syncthreads();
    for (int s = 128; s > 0; s >>= 1) {
        if (t < s) { st1[t] += st1[t + s]; scr[t] += scr[t + s]; }
        __syncthreads();
    }
    if (t == 0) {
        atomicAdd(&g_acc[0], st1[0]);
        atomicAdd(&g_acc[1], scr[0]);
    }
}

// ---------------- K7: finalize ---------------------------------------------
__global__ void k_final(float* __restrict__ out) {
    double m2 = 0.0;
    for (int k = 0; k < NC; k++) {
        double n = (double)g_cnt[k];
        m2 += n * n;
    }
    double loss = g_acc[0] / ((double)DD * (double)DD)
                - 2.0 * g_acc[1] / (double)DD
                + m2;
    out[0] = (float)loss;
}

// ---------------- launch ----------------------------------------------------
extern "C" void kernel_launch(void* const* d_in, const int* in_sizes, int n_in,
                              void* d_out, int out_size) {
    const float* za = (const float*)d_in[0];
    const float* zb = (const float*)d_in[1];
    const int* labels = (const int*)d_in[2];
    float* out = (float*)d_out;

    k_init<<<512, 256>>>(labels);
    k_scatter<<<16, 512>>>(labels);
    { dim3 g(64, 4, 2); k_convert_T<<<g, 256>>>(za, zb); }
    { dim3 g(4, 16, 2); k_clsgemm<<<g, 128>>>(); }
    { dim3 g(10, 32, 2); k_gram<<<g, 128>>>(); }
    k_stats<<<1, 512>>>();
    k_reduce<<<128, 256>>>();
    k_final<<<1, 1>>>(out);
}

// round 6
// speedup vs baseline: 3.1926x; 1.2776x over previous
#include <cuda_runtime.h>
#include <cuda_bf16.h>
#include <mma.h>
#include <cstdint>

using namespace nvcuda;

#define NN 8192
#define DD 512
#define NC 100
#define KSPLIT 16

// ---------------- scratch ---------------------------------------------------
__device__ __nv_bfloat16 g_z16t[2][DD * NN];        // transposed bf16: [d][n]
__device__ float  g_colsum[2][DD];
__device__ float  g_colsumsq[2][DD];
__device__ float  g_clsraw[2][NC * DD];             // raw per-class column sums
__device__ float  g_gpart[2 * KSPLIT * 10 * 16384]; // gram partials
__device__ float  g_mu[2][DD];
__device__ float  g_is[2][DD];
__device__ int    g_cnt[NC];
__device__ int    g_start[NC];
__device__ int    g_pos[NC];
__device__ int    g_order[NN];
__device__ int    g_is64;
__device__ double g_acc[2];

__device__ __forceinline__ int get_label(const int* L, int i) {
    return g_is64 ? L[2 * i] : L[i];
}

__device__ __forceinline__ uint32_t smem_u32(const void* p) {
    uint32_t a;
    asm("{ .reg .u64 t; cvta.to.shared.u64 t, %1; cvt.u32.u64 %0, t; }" : "=r"(a) : "l"(p));
    return a;
}
__device__ __forceinline__ void cp16(uint32_t dst, const void* src) {
    asm volatile("cp.async.cg.shared.global [%0], [%1], 16;" :: "r"(dst), "l"(src) : "memory");
}

// ---------------- K0: zero small accumulators, detect label dtype ----------
__global__ void k_init(const int* labels_raw) {
    int tid = blockIdx.x * blockDim.x + threadIdx.x;
    int stride = gridDim.x * blockDim.x;
    float* c1 = &g_colsum[0][0];
    float* c2 = &g_colsumsq[0][0];
    for (int i = tid; i < 2 * DD; i += stride) { c1[i] = 0.0f; c2[i] = 0.0f; }
    if (tid < NC) g_cnt[tid] = 0;
    if (tid < 2)  g_acc[tid] = 0.0;
    if (tid == 0) {
        int all0 = 1;
        for (int j = 1; j < 128; j += 2) if (labels_raw[j] != 0) { all0 = 0; break; }
        g_is64 = all0;
    }
}

// ---------------- K1: label histogram --------------------------------------
__global__ void k_hist(const int* __restrict__ labels) {
    __shared__ int h[NC];
    int t = threadIdx.x;
    if (t < NC) h[t] = 0;
    __syncthreads();
    int n = blockIdx.x * 512 + t;
    if (n < NN) atomicAdd(&h[get_label(labels, n)], 1);
    __syncthreads();
    if (t < NC && h[t]) atomicAdd(&g_cnt[t], h[t]);
}

// ---------------- K2: exclusive scan of counts -----------------------------
__global__ void k_scan(void) {
    if (threadIdx.x == 0) {
        int acc = 0;
        for (int k = 0; k < NC; k++) { g_start[k] = acc; g_pos[k] = acc; acc += g_cnt[k]; }
    }
}

// ---------------- K3: scatter sample indices grouped by class --------------
__global__ void k_order(const int* __restrict__ labels) {
    int n = blockIdx.x * 512 + threadIdx.x;
    if (n < NN) {
        int l = get_label(labels, n);
        int idx = atomicAdd(&g_pos[l], 1);
        g_order[idx] = n;
    }
}

// ---------------- K4: convert fp32 -> bf16 transposed + column stats -------
// grid (64 n-tiles, 4 d-tiles, 2), block 256
__global__ void k_convert_T(const float* __restrict__ za,
                            const float* __restrict__ zb) {
    int which = blockIdx.z;
    const float* z = which ? zb : za;
    __nv_bfloat16* o = g_z16t[which];

    __shared__ __nv_bfloat16 st[128 * 128];
    __shared__ float ssum[256], ssq[256];

    int t = threadIdx.x;
    int col = t & 127;
    int rh  = t >> 7;
    int n0 = blockIdx.x * 128;
    int d0 = blockIdx.y * 128;

    float s = 0.0f, sq = 0.0f;
    int sw = col & 15;
    for (int r = rh; r < 128; r += 2) {
        float v = z[(n0 + r) * DD + d0 + col];
        int idx = col * 128 + (((r >> 3) ^ sw) << 3) + (r & 7);
        st[idx] = __float2bfloat16(v);
        s += v; sq += v * v;
    }
    ssum[t] = s; ssq[t] = sq;
    __syncthreads();
    if (rh == 0) {
        atomicAdd(&g_colsum[which][d0 + col], ssum[t] + ssum[t + 128]);
        atomicAdd(&g_colsumsq[which][d0 + col], ssq[t] + ssq[t + 128]);
    }
    for (int v = t; v < 128 * 16; v += 256) {
        int dr = v >> 4;
        int og = v & 15;
        int pg = og ^ (dr & 15);
        uint4 val = *(const uint4*)&st[dr * 128 + pg * 8];
        *(uint4*)&o[(size_t)(d0 + dr) * NN + n0 + og * 8] = val;
    }
}

// ---------------- K5: per-class sums via sorted order ----------------------
// grid (4 dim-tiles, NC classes, 2), block 128
__global__ void __launch_bounds__(128) k_classsum(const float* __restrict__ za,
                                                  const float* __restrict__ zb) {
    int which = blockIdx.z;
    const float* z = which ? zb : za;
    int k  = blockIdx.y;
    int p0 = blockIdx.x * 128;
    int t  = threadIdx.x;

    int s0 = g_start[k];
    int cnt = g_cnt[k];

    __shared__ int sidx[256];
    float acc = 0.0f;
    for (int base = 0; base < cnt; base += 256) {
        int m = cnt - base; if (m > 256) m = 256;
        __syncthreads();
        for (int i = t; i < m; i += 128) sidx[i] = g_order[s0 + base + i];
        __syncthreads();
        for (int i = 0; i < m; i++)
            acc += z[(size_t)sidx[i] * DD + p0 + t];
    }
    g_clsraw[which][k * DD + p0 + t] = acc;
}

// ---------------- K6: Gram via wmma, cp.async double-buffered --------------
// upper-triangle 128x128 tiles; grid (10, KSPLIT, 2), block 256 (8 warps 2x4)
__constant__ int c_mt[10] = {0,0,0,0,1,1,1,2,2,3};
__constant__ int c_nt[10] = {0,1,2,3,1,2,3,2,3,3};

#define GSTRIDE 72                       // bf16 elems per smem row
#define GROWB   (GSTRIDE * 2)            // 144 bytes
#define GBUF    (128 * GROWB)            // 18432 bytes per tile buffer
#define GT_SMEM (4 * GBUF)               // A0 B0 A1 B1 = 73728 bytes

__global__ void __launch_bounds__(256) k_gram(void) {
    extern __shared__ char smem[];
    const int which = blockIdx.z;
    const int tile = blockIdx.x;
    const __nv_bfloat16* __restrict__ src = g_z16t[which];
    const __nv_bfloat16* __restrict__ srcA = src + (size_t)(c_mt[tile] * 128) * NN;
    const __nv_bfloat16* __restrict__ srcB = src + (size_t)(c_nt[tile] * 128) * NN;
    const int kbase = blockIdx.y * (NN / KSPLIT);   // 512 K per block

    const uint32_t sb = smem_u32(smem);
    const int t = threadIdx.x;
    const int warpId = t >> 5;
    const int wm = warpId & 1;      // 2 warps in m (64 each)
    const int wn = warpId >> 1;     // 4 warps in n (32 each)

    wmma::fragment<wmma::accumulator, 16, 16, 16, float> acc[4][2];
#pragma unroll
    for (int i = 0; i < 4; i++)
#pragma unroll
        for (int j = 0; j < 2; j++) wmma::fill_fragment(acc[i][j], 0.0f);

    // async stage of chunk c (64 K) into buffer c&1
    auto issue = [&](int c) {
        uint32_t abase = sb + (c & 1) * (2 * GBUF);
        uint32_t bbase = abase + GBUF;
        int koff = kbase + c * 64;
#pragma unroll
        for (int it = 0; it < 4; it++) {
            int idx = t + it * 256;          // 0..1023
            int row = idx >> 3, kv = idx & 7;
            uint32_t off = row * GROWB + kv * 16;
            cp16(abase + off, &srcA[(size_t)row * NN + koff + kv * 8]);
            cp16(bbase + off, &srcB[(size_t)row * NN + koff + kv * 8]);
        }
        asm volatile("cp.async.commit_group;" ::: "memory");
    };

    issue(0);
#pragma unroll 1
    for (int c = 0; c < 8; c++) {
        if (c + 1 < 8) {
            issue(c + 1);
            asm volatile("cp.async.wait_group 1;" ::: "memory");
        } else {
            asm volatile("cp.async.wait_group 0;" ::: "memory");
        }
        __syncthreads();

        const __nv_bfloat16* sA = (const __nv_bfloat16*)(smem + (c & 1) * (2 * GBUF));
        const __nv_bfloat16* sB = (const __nv_bfloat16*)(smem + (c & 1) * (2 * GBUF) + GBUF);
#pragma unroll
        for (int ks = 0; ks < 64; ks += 16) {
            wmma::fragment<wmma::matrix_a, 16, 16, 16, __nv_bfloat16, wmma::row_major> a_frag[4];
            wmma::fragment<wmma::matrix_b, 16, 16, 16, __nv_bfloat16, wmma::col_major> b_frag[2];
#pragma unroll
            for (int i = 0; i < 4; i++)
                wmma::load_matrix_sync(a_frag[i], sA + (wm * 64 + i * 16) * GSTRIDE + ks, GSTRIDE);
#pragma unroll
            for (int j = 0; j < 2; j++)
                wmma::load_matrix_sync(b_frag[j], sB + (wn * 32 + j * 16) * GSTRIDE + ks, GSTRIDE);
#pragma unroll
            for (int i = 0; i < 4; i++)
#pragma unroll
                for (int j = 0; j < 2; j++)
                    wmma::mma_sync(acc[i][j], a_frag[i], b_frag[j], acc[i][j]);
        }
        __syncthreads();
    }

    // epilogue: plain stores of this split's partial tile
    float* gp = g_gpart + (((size_t)which * KSPLIT + blockIdx.y) * 10 + tile) * 16384;
#pragma unroll
    for (int i = 0; i < 4; i++)
#pragma unroll
        for (int j = 0; j < 2; j++)
            wmma::store_matrix_sync(gp + (wm * 64 + i * 16) * 128 + wn * 32 + j * 16,
                                    acc[i][j], 128, wmma::mem_row_major);
}

// ---------------- K7: column stats -----------------------------------------
__global__ void k_stats(void) {
    int t = threadIdx.x;
    if (t < DD) {
#pragma unroll
        for (int w = 0; w < 2; w++) {
            float mu  = g_colsum[w][t] * (1.0f / (float)NN);
            float var = (g_colsumsq[w][t] - (float)NN * mu * mu) * (1.0f / (float)(NN - 1));
            g_mu[w][t] = mu;
            g_is[w][t] = (float)(1.0 / sqrt((double)var));
        }
    }
}

// ---------------- K8: reductions -------------------------------------------
__global__ void k_reduce(void) {
    int gid = blockIdx.x * 256 + threadIdx.x;
    const int GSZ = 128 * 256;

    const float* __restrict__ mua = g_mu[0];
    const float* __restrict__ mub = g_mu[1];
    const float* __restrict__ isa = g_is[0];
    const float* __restrict__ isb = g_is[1];

    double t1 = 0.0;
    for (int e = gid; e < 10 * 4096; e += GSZ) {
        int tile = e >> 12;
        int r = e & 4095;
        int i  = r >> 5;
        int j4 = (r & 31) << 2;
        int p  = c_mt[tile] * 128 + i;
        int qb = c_nt[tile] * 128 + j4;
        float w = (c_mt[tile] == c_nt[tile]) ? 1.0f : 2.0f;

        float4 ga = make_float4(0, 0, 0, 0), gb = make_float4(0, 0, 0, 0);
        size_t boff = (size_t)tile * 16384 + i * 128 + j4;
#pragma unroll
        for (int s = 0; s < KSPLIT; s++) {
            float4 va = *(const float4*)&g_gpart[((size_t)(0 * KSPLIT + s) * 10) * 16384 + boff];
            float4 vb = *(const float4*)&g_gpart[((size_t)(1 * KSPLIT + s) * 10) * 16384 + boff];
            ga.x += va.x; ga.y += va.y; ga.z += va.z; ga.w += va.w;
            gb.x += vb.x; gb.y += vb.y; gb.z += vb.z; gb.w += vb.w;
        }
        float4 qia = *(const float4*)&isa[qb];
        float4 qma = *(const float4*)&mua[qb];
        float4 qib = *(const float4*)&isb[qb];
        float4 qmb = *(const float4*)&mub[qb];
        float pia = isa[p], pma = mua[p], pib = isb[p], pmb = mub[p];

        float ax = pia * qia.x * (ga.x - (float)NN * pma * qma.x);
        float ay = pia * qia.y * (ga.y - (float)NN * pma * qma.y);
        float az = pia * qia.z * (ga.z - (float)NN * pma * qma.z);
        float aw = pia * qia.w * (ga.w - (float)NN * pma * qma.w);
        float bx = pib * qib.x * (gb.x - (float)NN * pmb * qmb.x);
        float by = pib * qib.y * (gb.y - (float)NN * pmb * qmb.y);
        float bz = pib * qib.z * (gb.z - (float)NN * pmb * qmb.z);
        float bw = pib * qib.w * (gb.w - (float)NN * pmb * qmb.w);
        t1 += (double)(w * (ax * bx + ay * by + az * bz + aw * bw));
    }

    double cr = 0.0;
    for (int idx = gid; idx < NC * DD; idx += GSZ) {
        int k = idx >> 9, p = idx & (DD - 1);
        float nk = (float)g_cnt[k];
        float u = isa[p] * (g_clsraw[0][idx] - nk * mua[p]);
        float v = isb[p] * (g_clsraw[1][idx] - nk * mub[p]);
        cr += (double)(u * v);
    }

    __shared__ double st1[256], scr[256];
    int t = threadIdx.x;
    st1[t] = t1; scr[t] = cr;
    __syncthreads();
    for (int s = 128; s > 0; s >>= 1) {
        if (t < s) { st1[t] += st1[t + s]; scr[t] += scr[t + s]; }
        __syncthreads();
    }
    if (t == 0) {
        atomicAdd(&g_acc[0], st1[0]);
        atomicAdd(&g_acc[1], scr[0]);
    }
}

// ---------------- K9: finalize ---------------------------------------------
__global__ void k_final(float* __restrict__ out) {
    double m2 = 0.0;
    for (int k = 0; k < NC; k++) {
        double n = (double)g_cnt[k];
        m2 += n * n;
    }
    double loss = g_acc[0] / ((double)DD * (double)DD)
                - 2.0 * g_acc[1] / (double)DD
                + m2;
    out[0] = (float)loss;
}

// ---------------- launch ----------------------------------------------------
extern "C" void kernel_launch(void* const* d_in, const int* in_sizes, int n_in,
                              void* d_out, int out_size) {
    const float* za = (const float*)d_in[0];
    const float* zb = (const float*)d_in[1];
    const int* labels = (const int*)d_in[2];
    float* out = (float*)d_out;

    static int smem_set = 0;
    if (!smem_set) {
        cudaFuncSetAttribute(k_gram, cudaFuncAttributeMaxDynamicSharedMemorySize, GT_SMEM);
        smem_set = 1;
    }

    k_init<<<4, 256>>>(labels);
    k_hist<<<16, 512>>>(labels);
    k_scan<<<1, 32>>>();
    k_order<<<16, 512>>>(labels);
    { dim3 g(64, 4, 2); k_convert_T<<<g, 256>>>(za, zb); }
    { dim3 g(4, NC, 2); k_classsum<<<g, 128>>>(za, zb); }
    { dim3 g(10, KSPLIT, 2); k_gram<<<g, 256, GT_SMEM>>>(); }
    k_stats<<<1, 512>>>();
    k_reduce<<<128, 256>>>();
    k_final<<<1, 1>>>(out);
}